// round 12
// baseline (speedup 1.0000x reference)
#include <cuda_runtime.h>
#include <math.h>

#define BB 32
#define TT 4096
#define FF 256
#define KSEL 409            // max(1, int(4096*0.1))
#define RPW 8               // rows per warp in kA
#define RPB 64              // rows per block in kA
#define NCHUNK (TT/RPB)     // 64
#define NS 32               // gather slices (rank-partitioned)
#define SLICE 13            // ceil(KSEL/NS)

__device__ float    g_w[BB*TT];
__device__ float    g_part[BB*NCHUNK*FF];
__device__ float    g_corr[BB*NS*FF];
__device__ int      g_idx[BB*KSEL];
__device__ float    g_wv[BB*KSEL];
__device__ float    g_invZ[BB];
__device__ int      g_flag[BB];       // zero-init; self-resetting
__device__ int      g_cntG[BB];       // zero-init; self-resetting

__device__ __forceinline__ int ld_acquire(const int* p) {
    int v;
    asm volatile("ld.acquire.gpu.b32 %0, [%1];" : "=r"(v) : "l"(p));
    return v;
}
__device__ __forceinline__ void st_release(int* p, int v) {
    asm volatile("st.release.gpu.b32 [%0], %1;" :: "l"(p), "r"(v));
}

// ==== Kernel A: single-pass fused dot + weighted feature sum (R11 measured-best) ====
__global__ void __launch_bounds__(256) kA(const float* __restrict__ x,
                                          const float* __restrict__ W,
                                          const float* __restrict__ bias) {
    __shared__ float4 sacc[8][64];
    const int c = blockIdx.x, b = blockIdx.y;
    const int tid = threadIdx.x;
    const int warp = tid >> 5, lane = tid & 31;

    const float4* wr = (const float4*)W;
    const float4 w0 = __ldg(&wr[lane]);
    const float4 w1 = __ldg(&wr[lane + 32]);
    const float bias0 = bias[0];

    const int row0 = c * RPB + warp * RPW;
    const float4* xg = (const float4*)(x + ((size_t)b*TT + row0) * FF);

    float4 ac0 = make_float4(0.f,0.f,0.f,0.f);
    float4 ac1 = make_float4(0.f,0.f,0.f,0.f);
    float wkeep = 0.f;

    #pragma unroll 4
    for (int r = 0; r < RPW; r++) {
        const float4 a0 = xg[(size_t)r*64 + lane];
        const float4 a1 = xg[(size_t)r*64 + 32 + lane];
        float s = a0.x*w0.x + a0.y*w0.y + a0.z*w0.z + a0.w*w0.w
                + a1.x*w1.x + a1.y*w1.y + a1.z*w1.z + a1.w*w1.w;
        #pragma unroll
        for (int o = 16; o; o >>= 1) s += __shfl_xor_sync(0xffffffffu, s, o);
        const float wv = __expf(tanhf(s + bias0) - 1.0f);  // shift by max=1
        if (lane == r) wkeep = wv;
        ac0.x += a0.x*wv; ac0.y += a0.y*wv; ac0.z += a0.z*wv; ac0.w += a0.w*wv;
        ac1.x += a1.x*wv; ac1.y += a1.y*wv; ac1.z += a1.z*wv; ac1.w += a1.w*wv;
    }
    if (lane < RPW) g_w[b*TT + row0 + lane] = wkeep;

    sacc[warp][lane]      = ac0;
    sacc[warp][32 + lane] = ac1;
    __syncthreads();

    const int f4 = tid & 63, h = tid >> 6;
    if (h == 0) {
        float4 s = sacc[0][f4];
        #pragma unroll
        for (int wdx = 1; wdx < 8; wdx++) {
            float4 t = sacc[wdx][f4];
            s.x += t.x; s.y += t.y; s.z += t.z; s.w += t.w;
        }
        ((float4*)g_part)[((size_t)b*NCHUNK + c)*64 + f4] = s;
    }
}

// ==== Kernel SG: fused select (32 blocks) + gather (1024 blocks) + combine ====
// 1D grid of 32 + NS*32 blocks. Selector blocks have the lowest bids, so they
// are scheduled first; gather blocks spin on a per-batch release flag.
__global__ void __launch_bounds__(256) kSG(const float* __restrict__ x,
                                           float* __restrict__ out) {
    const int bid = blockIdx.x, tid = threadIdx.x;
    const int lane = tid & 31, wid = tid >> 5;

    if (bid < BB) {
        // ---------------- selector for batch b ----------------
        __shared__ float    red[256];
        __shared__ unsigned cnt[32];
        __shared__ unsigned wtot[8];
        const int b = bid;

        unsigned key[16];
        float zsum = 0.f;
        #pragma unroll
        for (int i = 0; i < 16; i++) {
            float w = g_w[b*TT + tid + i*256];
            key[i] = __float_as_uint(w);   // w in (e^-2,1]: bits order-preserving
            zsum += w;
        }
        red[tid] = zsum;
        if (tid < 32) cnt[tid] = 0;
        __syncthreads();
        #pragma unroll
        for (int o = 128; o; o >>= 1) {
            if (tid < o) red[tid] += red[tid + o];
            __syncthreads();
        }
        if (tid == 0) g_invZ[b] = 1.0f / red[0];

        // w in (e^-2,1]: bits 31,30=0 and 29..25=11111 -> bisect bits 24..0
        unsigned prefix = 0x3E000000u;
        for (int bit = 24; bit >= 0; bit--) {
            const unsigned test = prefix | (1u << bit);
            unsigned c = 0;
            #pragma unroll
            for (int i = 0; i < 16; i++) c += (key[i] >= test);
            c = __reduce_add_sync(0xffffffffu, c);
            if (lane == 0) atomicAdd(&cnt[bit], c);
            __syncthreads();
            if (cnt[bit] >= KSEL) prefix = test;   // unique counter per bit
        }

        // deterministic compaction of (index, weight)
        unsigned tc = 0;
        #pragma unroll
        for (int i = 0; i < 16; i++) tc += (key[i] >= prefix);
        unsigned inc = tc;
        #pragma unroll
        for (int o = 1; o < 32; o <<= 1) {
            unsigned v = __shfl_up_sync(0xffffffffu, inc, o);
            if (lane >= o) inc += v;
        }
        if (lane == 31) wtot[wid] = inc;
        __syncthreads();
        if (tid == 0) {
            unsigned s = 0;
            #pragma unroll
            for (int j = 0; j < 8; j++) { unsigned t = wtot[j]; wtot[j] = s; s += t; }
        }
        __syncthreads();
        unsigned pos = wtot[wid] + inc - tc;
        #pragma unroll
        for (int i = 0; i < 16; i++) {
            if (key[i] >= prefix) {
                if (pos < KSEL) {
                    g_idx[b*KSEL + pos] = tid + i*256;
                    g_wv[b*KSEL + pos]  = __uint_as_float(key[i]);
                }
                pos++;
            }
        }
        __threadfence();
        __syncthreads();
        if (tid == 0) st_release(&g_flag[b], 1);
        return;
    }

    // ---------------- gather block: slice s of batch b ----------------
    __shared__ int    idx_sh[SLICE];
    __shared__ float  wv_sh[SLICE];
    __shared__ float4 acc_sh[256];
    __shared__ int    lastf;
    const int gidx = bid - BB;
    const int b = gidx & 31;
    const int s = gidx >> 5;
    const int p0 = s * SLICE;
    const int n  = min(KSEL - p0, SLICE);

    if (tid == 0) {
        while (ld_acquire(&g_flag[b]) == 0) __nanosleep(128);
    }
    __syncthreads();                         // all threads see flag's release

    if (tid < n) {
        idx_sh[tid] = g_idx[b*KSEL + p0 + tid];
        wv_sh[tid]  = g_wv[b*KSEL + p0 + tid];
    }
    __syncthreads();

    const int f4 = tid & 63;        // float4 feature group
    const int h  = tid >> 6;        // 0..3 phase over the index list
    const float4* xb4 = ((const float4*)(x + (size_t)b*TT*FF)) + f4;
    float4 a = make_float4(0.f,0.f,0.f,0.f);
    #pragma unroll 4
    for (int p = h; p < n; p += 4) {          // dense, unconditional loads
        const float4 v = xb4[(size_t)idx_sh[p] * 64];
        const float wv = wv_sh[p];
        a.x += v.x*wv; a.y += v.y*wv; a.z += v.z*wv; a.w += v.w*wv;
    }
    acc_sh[tid] = a;
    __syncthreads();
    if (h == 0) {
        float4 v = acc_sh[f4];
        #pragma unroll
        for (int j = 1; j < 4; j++) {
            float4 t = acc_sh[j*64 + f4];
            v.x += t.x; v.y += t.y; v.z += t.z; v.w += t.w;
        }
        ((float4*)g_corr)[((size_t)b*NS + s)*64 + f4] = v;
    }

    // last gather block of batch b combines (fixed read order -> deterministic)
    __threadfence();
    __syncthreads();
    if (tid == 0) lastf = (atomicAdd(&g_cntG[b], 1) == NS - 1);
    __syncthreads();
    if (!lastf) return;
    __threadfence();

    const int f = tid;
    float s1 = 0.f, sc = 0.f;
    #pragma unroll 8
    for (int c = 0; c < NCHUNK; c++) s1 += g_part[(b*NCHUNK + c)*FF + f];
    #pragma unroll 8
    for (int ss = 0; ss < NS; ss++) sc += g_corr[(b*NS + ss)*FF + f];
    out[b*FF + f] = (s1 + 0.5f * sc) * g_invZ[b];
    if (tid == 0) {                          // reset for next graph replay
        g_cntG[b] = 0;
        g_flag[b] = 0;
    }
}

extern "C" void kernel_launch(void* const* d_in, const int* in_sizes, int n_in,
                              void* d_out, int out_size) {
    const float* x    = (const float*)d_in[0];
    const float* W    = (const float*)d_in[1];
    const float* bias = (const float*)d_in[2];
    float* out = (float*)d_out;

    dim3 gA(NCHUNK, BB);
    kA<<<gA, 256>>>(x, W, bias);
    kSG<<<BB + NS*BB, 256>>>(x, out);
}

// round 13
// speedup vs baseline: 1.2824x; 1.2824x over previous
#include <cuda_runtime.h>
#include <math.h>

#define BB 32
#define TT 4096
#define FF 256
#define KSEL 409            // max(1, int(4096*0.1))
#define RPW 8               // rows per warp in kA
#define RPB 64              // rows per block in kA
#define NCHUNK (TT/RPB)     // 64
#define NS 32               // gather slices (rank-partitioned)
#define SLICE 13            // ceil(KSEL/NS)

__device__ float    g_w[BB*TT];
__device__ float    g_part[BB*NCHUNK*FF];
__device__ float    g_corr[BB*NS*FF];
__device__ int      g_idx[BB*KSEL];
__device__ float    g_wv[BB*KSEL];
__device__ float    g_invZ[BB];
__device__ int      g_cntG[BB];       // zero-init; self-resetting

// ==== Kernel A: single-pass fused dot + weighted feature sum (R11 measured-best) ====
__global__ void __launch_bounds__(256) kA(const float* __restrict__ x,
                                          const float* __restrict__ W,
                                          const float* __restrict__ bias) {
    __shared__ float4 sacc[8][64];
    const int c = blockIdx.x, b = blockIdx.y;
    const int tid = threadIdx.x;
    const int warp = tid >> 5, lane = tid & 31;

    const float4* wr = (const float4*)W;
    const float4 w0 = __ldg(&wr[lane]);
    const float4 w1 = __ldg(&wr[lane + 32]);
    const float bias0 = bias[0];

    const int row0 = c * RPB + warp * RPW;
    const float4* xg = (const float4*)(x + ((size_t)b*TT + row0) * FF);

    float4 ac0 = make_float4(0.f,0.f,0.f,0.f);
    float4 ac1 = make_float4(0.f,0.f,0.f,0.f);
    float wkeep = 0.f;

    #pragma unroll 4
    for (int r = 0; r < RPW; r++) {
        const float4 a0 = xg[(size_t)r*64 + lane];
        const float4 a1 = xg[(size_t)r*64 + 32 + lane];
        float s = a0.x*w0.x + a0.y*w0.y + a0.z*w0.z + a0.w*w0.w
                + a1.x*w1.x + a1.y*w1.y + a1.z*w1.z + a1.w*w1.w;
        #pragma unroll
        for (int o = 16; o; o >>= 1) s += __shfl_xor_sync(0xffffffffu, s, o);
        const float wv = __expf(tanhf(s + bias0) - 1.0f);  // shift by max=1
        if (lane == r) wkeep = wv;
        ac0.x += a0.x*wv; ac0.y += a0.y*wv; ac0.z += a0.z*wv; ac0.w += a0.w*wv;
        ac1.x += a1.x*wv; ac1.y += a1.y*wv; ac1.z += a1.z*wv; ac1.w += a1.w*wv;
    }
    if (lane < RPW) g_w[b*TT + row0 + lane] = wkeep;

    sacc[warp][lane]      = ac0;
    sacc[warp][32 + lane] = ac1;
    __syncthreads();

    const int f4 = tid & 63, h = tid >> 6;
    if (h == 0) {
        float4 s = sacc[0][f4];
        #pragma unroll
        for (int wdx = 1; wdx < 8; wdx++) {
            float4 t = sacc[wdx][f4];
            s.x += t.x; s.y += t.y; s.z += t.z; s.w += t.w;
        }
        ((float4*)g_part)[((size_t)b*NCHUNK + c)*64 + f4] = s;
    }
    cudaTriggerProgrammaticLaunchCompletion();
}

// ==== Kernel B: Z + exact k-th largest + deterministic compaction ====
__global__ void __launch_bounds__(512) kB(void) {
    __shared__ float    red[512];
    __shared__ unsigned cnt[32];
    __shared__ unsigned wtot[16];
    const int b = blockIdx.x, tid = threadIdx.x;
    const int lane = tid & 31, wid = tid >> 5;

    cudaGridDependencySynchronize();        // wait for kA's memory

    unsigned key[8];
    float zsum = 0.f;
    #pragma unroll
    for (int i = 0; i < 8; i++) {
        float w = g_w[b*TT + tid + i*512];
        key[i] = __float_as_uint(w);       // w in (e^-2,1]: bits order-preserving
        zsum += w;
    }
    red[tid] = zsum;
    if (tid < 32) cnt[tid] = 0;
    __syncthreads();
    #pragma unroll
    for (int o = 256; o; o >>= 1) {
        if (tid < o) red[tid] += red[tid + o];
        __syncthreads();
    }
    if (tid == 0) g_invZ[b] = 1.0f / red[0];

    // w in (e^-2,1]: bits 31,30=0 and 29..25=11111 -> bisect bits 24..0
    unsigned prefix = 0x3E000000u;
    for (int bit = 24; bit >= 0; bit--) {
        const unsigned test = prefix | (1u << bit);
        unsigned c = 0;
        #pragma unroll
        for (int i = 0; i < 8; i++) c += (key[i] >= test);
        c = __reduce_add_sync(0xffffffffu, c);
        if (lane == 0) atomicAdd(&cnt[bit], c);
        __syncthreads();
        if (cnt[bit] >= KSEL) prefix = test;   // unique counter per bit
    }

    // deterministic compaction of (index, weight)
    unsigned tc = 0;
    #pragma unroll
    for (int i = 0; i < 8; i++) tc += (key[i] >= prefix);
    unsigned inc = tc;
    #pragma unroll
    for (int o = 1; o < 32; o <<= 1) {
        unsigned v = __shfl_up_sync(0xffffffffu, inc, o);
        if (lane >= o) inc += v;
    }
    if (lane == 31) wtot[wid] = inc;
    __syncthreads();
    if (tid == 0) {
        unsigned s = 0;
        #pragma unroll
        for (int j = 0; j < 16; j++) { unsigned t = wtot[j]; wtot[j] = s; s += t; }
    }
    __syncthreads();
    unsigned pos = wtot[wid] + inc - tc;
    #pragma unroll
    for (int i = 0; i < 8; i++) {
        if (key[i] >= prefix) {
            if (pos < KSEL) {
                g_idx[b*KSEL + pos] = tid + i*512;
                g_wv[b*KSEL + pos]  = __uint_as_float(key[i]);
            }
            pos++;
        }
    }
    cudaTriggerProgrammaticLaunchCompletion();
}

// ==== Kernel G: dense rank-sliced gather + last-block combine ====
__global__ void __launch_bounds__(256) kG(const float* __restrict__ x,
                                          float* __restrict__ out) {
    __shared__ int    idx_sh[SLICE];
    __shared__ float  wv_sh[SLICE];
    __shared__ float4 acc_sh[256];
    __shared__ int    lastf;
    const int s = blockIdx.x, b = blockIdx.y, tid = threadIdx.x;
    const int p0 = s * SLICE;
    const int n  = min(KSEL - p0, SLICE);

    cudaGridDependencySynchronize();        // wait for kB's memory

    if (tid < n) {
        idx_sh[tid] = g_idx[b*KSEL + p0 + tid];
        wv_sh[tid]  = g_wv[b*KSEL + p0 + tid];
    }
    __syncthreads();

    const int f4 = tid & 63;        // float4 feature group
    const int h  = tid >> 6;        // 0..3 phase over the index list
    const float4* xb4 = ((const float4*)(x + (size_t)b*TT*FF)) + f4;
    float4 a = make_float4(0.f,0.f,0.f,0.f);
    #pragma unroll 4
    for (int p = h; p < n; p += 4) {          // dense, unconditional loads
        const float4 v = xb4[(size_t)idx_sh[p] * 64];
        const float wv = wv_sh[p];
        a.x += v.x*wv; a.y += v.y*wv; a.z += v.z*wv; a.w += v.w*wv;
    }
    acc_sh[tid] = a;
    __syncthreads();
    if (h == 0) {
        float4 v = acc_sh[f4];
        #pragma unroll
        for (int j = 1; j < 4; j++) {
            float4 t = acc_sh[j*64 + f4];
            v.x += t.x; v.y += t.y; v.z += t.z; v.w += t.w;
        }
        ((float4*)g_corr)[((size_t)b*NS + s)*64 + f4] = v;
    }

    // last block per batch combines (fixed read order -> deterministic)
    __threadfence();
    __syncthreads();
    if (tid == 0) lastf = (atomicAdd(&g_cntG[b], 1) == NS - 1);
    __syncthreads();
    if (!lastf) return;
    __threadfence();

    const int f = tid;
    float s1 = 0.f, sc = 0.f;
    #pragma unroll 8
    for (int c = 0; c < NCHUNK; c++) s1 += g_part[(b*NCHUNK + c)*FF + f];
    #pragma unroll 8
    for (int ss = 0; ss < NS; ss++) sc += g_corr[(b*NS + ss)*FF + f];
    out[b*FF + f] = (s1 + 0.5f * sc) * g_invZ[b];
    if (tid == 0) g_cntG[b] = 0;            // reset for next graph replay
}

extern "C" void kernel_launch(void* const* d_in, const int* in_sizes, int n_in,
                              void* d_out, int out_size) {
    const float* x    = (const float*)d_in[0];
    const float* W    = (const float*)d_in[1];
    const float* bias = (const float*)d_in[2];
    float* out = (float*)d_out;

    // kA: normal launch
    dim3 gA(NCHUNK, BB);
    kA<<<gA, 256>>>(x, W, bias);

    // kB, kG: programmatic dependent launch (overlap launch latency)
    cudaLaunchAttribute at[1];
    at[0].id = cudaLaunchAttributeProgrammaticStreamSerialization;
    at[0].val.programmaticStreamSerializationAllowed = 1;

    cudaLaunchConfig_t cfgB = {};
    cfgB.gridDim  = dim3(BB, 1, 1);
    cfgB.blockDim = dim3(512, 1, 1);
    cfgB.attrs = at;
    cfgB.numAttrs = 1;
    cudaLaunchKernelEx(&cfgB, kB);

    cudaLaunchConfig_t cfgG = {};
    cfgG.gridDim  = dim3(NS, BB, 1);
    cfgG.blockDim = dim3(256, 1, 1);
    cfgG.attrs = at;
    cfgG.numAttrs = 1;
    cudaLaunchKernelEx(&cfgG, kG, x, out);
}

// round 14
// speedup vs baseline: 1.4156x; 1.1039x over previous
#include <cuda_runtime.h>
#include <math.h>

#define BB 32
#define TT 4096
#define FF 256
#define KSEL 409            // max(1, int(4096*0.1))
#define RPW 8               // rows per warp in kA
#define RPB 64              // rows per block in kA
#define NCHUNK (TT/RPB)     // 64
#define NS 32               // gather slices (rank-partitioned)
#define SLICE 13            // ceil(KSEL/NS)

__device__ float    g_w[BB*TT];
__device__ float    g_part[BB*NCHUNK*FF];
__device__ float    g_corr[BB*NS*FF];
__device__ int      g_idx[BB*KSEL];
__device__ float    g_wv[BB*KSEL];
__device__ float    g_invZ[BB];

// ==== Kernel A: single-pass fused dot + weighted feature sum (measured-best) ====
__global__ void __launch_bounds__(256) kA(const float* __restrict__ x,
                                          const float* __restrict__ W,
                                          const float* __restrict__ bias) {
    __shared__ float4 sacc[8][64];
    const int c = blockIdx.x, b = blockIdx.y;
    const int tid = threadIdx.x;
    const int warp = tid >> 5, lane = tid & 31;

    const float4* wr = (const float4*)W;
    const float4 w0 = __ldg(&wr[lane]);
    const float4 w1 = __ldg(&wr[lane + 32]);
    const float bias0 = bias[0];

    const int row0 = c * RPB + warp * RPW;
    const float4* xg = (const float4*)(x + ((size_t)b*TT + row0) * FF);

    float4 ac0 = make_float4(0.f,0.f,0.f,0.f);
    float4 ac1 = make_float4(0.f,0.f,0.f,0.f);
    float wkeep = 0.f;

    #pragma unroll 4
    for (int r = 0; r < RPW; r++) {
        const float4 a0 = xg[(size_t)r*64 + lane];
        const float4 a1 = xg[(size_t)r*64 + 32 + lane];
        float s = a0.x*w0.x + a0.y*w0.y + a0.z*w0.z + a0.w*w0.w
                + a1.x*w1.x + a1.y*w1.y + a1.z*w1.z + a1.w*w1.w;
        #pragma unroll
        for (int o = 16; o; o >>= 1) s += __shfl_xor_sync(0xffffffffu, s, o);
        const float wv = __expf(tanhf(s + bias0) - 1.0f);  // shift by max=1
        if (lane == r) wkeep = wv;
        ac0.x += a0.x*wv; ac0.y += a0.y*wv; ac0.z += a0.z*wv; ac0.w += a0.w*wv;
        ac1.x += a1.x*wv; ac1.y += a1.y*wv; ac1.z += a1.z*wv; ac1.w += a1.w*wv;
    }
    if (lane < RPW) g_w[b*TT + row0 + lane] = wkeep;

    sacc[warp][lane]      = ac0;
    sacc[warp][32 + lane] = ac1;
    __syncthreads();

    const int f4 = tid & 63, h = tid >> 6;
    if (h == 0) {
        float4 s = sacc[0][f4];
        #pragma unroll
        for (int wdx = 1; wdx < 8; wdx++) {
            float4 t = sacc[wdx][f4];
            s.x += t.x; s.y += t.y; s.z += t.z; s.w += t.w;
        }
        ((float4*)g_part)[((size_t)b*NCHUNK + c)*64 + f4] = s;
    }
    cudaTriggerProgrammaticLaunchCompletion();
}

// ==== Kernel B: 2-bit radix select (13 rounds, Z-tree interleaved) + compaction ====
__global__ void __launch_bounds__(512) kB(void) {
    __shared__ float    red[512];
    __shared__ unsigned cnt[40];
    __shared__ unsigned wtot[16];
    const int b = blockIdx.x, tid = threadIdx.x;
    const int lane = tid & 31, wid = tid >> 5;

    cudaGridDependencySynchronize();        // wait for kA's memory

    unsigned key[8];
    float zsum = 0.f;
    #pragma unroll
    for (int i = 0; i < 8; i++) {
        float w = g_w[b*TT + tid + i*512];
        key[i] = __float_as_uint(w);       // w in (e^-2,1]: bits order-preserving
        zsum += w;
    }
    red[tid] = zsum;
    if (tid < 40) cnt[tid] = 0;
    __syncthreads();

    // bits 31..25 fixed (0x3E000000 pattern) for w in (e^-2,1];
    // bisect bits 24..0: 12 2-bit rounds (bits 24..1) + 1 final 1-bit round.
    unsigned prefix = 0x3E000000u;
    #pragma unroll
    for (int r = 0; r < 12; r++) {
        const int lo = 23 - 2*r;
        const unsigned t1 = prefix | (1u << lo);
        const unsigned t2 = prefix | (2u << lo);
        const unsigned t3 = prefix | (3u << lo);
        unsigned c1 = 0, c2 = 0, c3 = 0;
        #pragma unroll
        for (int i = 0; i < 8; i++) {
            c1 += (key[i] >= t1);
            c2 += (key[i] >= t2);
            c3 += (key[i] >= t3);
        }
        c1 = __reduce_add_sync(0xffffffffu, c1);
        c2 = __reduce_add_sync(0xffffffffu, c2);
        c3 = __reduce_add_sync(0xffffffffu, c3);
        if (lane == 0) {
            atomicAdd(&cnt[3*r + 0], c1);
            atomicAdd(&cnt[3*r + 1], c2);
            atomicAdd(&cnt[3*r + 2], c3);
        }
        // interleaved Z-tree step (reads separated from writes by round barrier)
        if (r < 9) {
            const int o = 256 >> r;
            if (tid < o) red[tid] += red[tid + o];
        }
        __syncthreads();
        if      (cnt[3*r + 2] >= KSEL) prefix = t3;
        else if (cnt[3*r + 1] >= KSEL) prefix = t2;
        else if (cnt[3*r + 0] >= KSEL) prefix = t1;
    }
    {   // final bit 0
        const unsigned t = prefix | 1u;
        unsigned c = 0;
        #pragma unroll
        for (int i = 0; i < 8; i++) c += (key[i] >= t);
        c = __reduce_add_sync(0xffffffffu, c);
        if (lane == 0) atomicAdd(&cnt[36], c);
        __syncthreads();
        if (cnt[36] >= KSEL) prefix = t;
    }
    if (tid == 0) g_invZ[b] = 1.0f / red[0];

    // deterministic compaction of (index, weight)
    unsigned tc = 0;
    #pragma unroll
    for (int i = 0; i < 8; i++) tc += (key[i] >= prefix);
    unsigned inc = tc;
    #pragma unroll
    for (int o = 1; o < 32; o <<= 1) {
        unsigned v = __shfl_up_sync(0xffffffffu, inc, o);
        if (lane >= o) inc += v;
    }
    if (lane == 31) wtot[wid] = inc;
    __syncthreads();
    if (tid == 0) {
        unsigned s = 0;
        #pragma unroll
        for (int j = 0; j < 16; j++) { unsigned t = wtot[j]; wtot[j] = s; s += t; }
    }
    __syncthreads();
    unsigned pos = wtot[wid] + inc - tc;
    #pragma unroll
    for (int i = 0; i < 8; i++) {
        if (key[i] >= prefix) {
            if (pos < KSEL) {
                g_idx[b*KSEL + pos] = tid + i*512;
                g_wv[b*KSEL + pos]  = __uint_as_float(key[i]);
            }
            pos++;
        }
    }
    cudaTriggerProgrammaticLaunchCompletion();
}

// ==== Kernel G: dense rank-sliced gather (no combine; retires immediately) ====
__global__ void __launch_bounds__(256) kG(const float* __restrict__ x) {
    __shared__ int    idx_sh[SLICE];
    __shared__ float  wv_sh[SLICE];
    __shared__ float4 acc_sh[256];
    const int s = blockIdx.x, b = blockIdx.y, tid = threadIdx.x;
    const int p0 = s * SLICE;
    const int n  = min(KSEL - p0, SLICE);

    cudaGridDependencySynchronize();        // wait for kB's memory

    if (tid < n) {
        idx_sh[tid] = g_idx[b*KSEL + p0 + tid];
        wv_sh[tid]  = g_wv[b*KSEL + p0 + tid];
    }
    __syncthreads();

    const int f4 = tid & 63;        // float4 feature group
    const int h  = tid >> 6;        // 0..3 phase over the index list
    const float4* xb4 = ((const float4*)(x + (size_t)b*TT*FF)) + f4;
    float4 a = make_float4(0.f,0.f,0.f,0.f);
    #pragma unroll 4
    for (int p = h; p < n; p += 4) {          // dense, unconditional loads
        const float4 v = xb4[(size_t)idx_sh[p] * 64];
        const float wv = wv_sh[p];
        a.x += v.x*wv; a.y += v.y*wv; a.z += v.z*wv; a.w += v.w*wv;
    }
    acc_sh[tid] = a;
    __syncthreads();
    if (h == 0) {
        float4 v = acc_sh[f4];
        #pragma unroll
        for (int j = 1; j < 4; j++) {
            float4 t = acc_sh[j*64 + f4];
            v.x += t.x; v.y += t.y; v.z += t.z; v.w += t.w;
        }
        ((float4*)g_corr)[((size_t)b*NS + s)*64 + f4] = v;
    }
    cudaTriggerProgrammaticLaunchCompletion();
}

// ==== Kernel D: combine partials + corrections, scale by 1/Z ====
__global__ void __launch_bounds__(256) kD(float* __restrict__ out) {
    __shared__ float4 acc_sh[256];
    const int b = blockIdx.x, tid = threadIdx.x;
    const int f4 = tid & 63, h = tid >> 6;   // 4 phases

    cudaGridDependencySynchronize();        // wait for kG's memory

    const float4* part4 = ((const float4*)g_part) + (size_t)b*NCHUNK*64 + f4;
    float4 a = make_float4(0.f,0.f,0.f,0.f);
    #pragma unroll
    for (int c = h; c < NCHUNK; c += 4) {
        float4 v = part4[(size_t)c*64];
        a.x += v.x; a.y += v.y; a.z += v.z; a.w += v.w;
    }
    const float4* corr4 = ((const float4*)g_corr) + (size_t)b*NS*64 + f4;
    float4 ac = make_float4(0.f,0.f,0.f,0.f);
    #pragma unroll
    for (int s = h; s < NS; s += 4) {
        float4 v = corr4[(size_t)s*64];
        ac.x += v.x; ac.y += v.y; ac.z += v.z; ac.w += v.w;
    }
    a.x += 0.5f*ac.x; a.y += 0.5f*ac.y; a.z += 0.5f*ac.z; a.w += 0.5f*ac.w;
    acc_sh[tid] = a;
    __syncthreads();
    if (h == 0) {
        const float invZ = g_invZ[b];
        float4 s = acc_sh[f4];
        #pragma unroll
        for (int j = 1; j < 4; j++) {
            float4 t = acc_sh[j*64 + f4];
            s.x += t.x; s.y += t.y; s.z += t.z; s.w += t.w;
        }
        s.x *= invZ; s.y *= invZ; s.z *= invZ; s.w *= invZ;
        ((float4*)out)[b*64 + f4] = s;
    }
}

extern "C" void kernel_launch(void* const* d_in, const int* in_sizes, int n_in,
                              void* d_out, int out_size) {
    const float* x    = (const float*)d_in[0];
    const float* W    = (const float*)d_in[1];
    const float* bias = (const float*)d_in[2];
    float* out = (float*)d_out;

    dim3 gA(NCHUNK, BB);
    kA<<<gA, 256>>>(x, W, bias);

    cudaLaunchAttribute at[1];
    at[0].id = cudaLaunchAttributeProgrammaticStreamSerialization;
    at[0].val.programmaticStreamSerializationAllowed = 1;

    cudaLaunchConfig_t cfgB = {};
    cfgB.gridDim  = dim3(BB, 1, 1);
    cfgB.blockDim = dim3(512, 1, 1);
    cfgB.attrs = at;  cfgB.numAttrs = 1;
    cudaLaunchKernelEx(&cfgB, kB);

    cudaLaunchConfig_t cfgG = {};
    cfgG.gridDim  = dim3(NS, BB, 1);
    cfgG.blockDim = dim3(256, 1, 1);
    cfgG.attrs = at;  cfgG.numAttrs = 1;
    cudaLaunchKernelEx(&cfgG, kG, x);

    cudaLaunchConfig_t cfgD = {};
    cfgD.gridDim  = dim3(BB, 1, 1);
    cfgD.blockDim = dim3(256, 1, 1);
    cfgD.attrs = at;  cfgD.numAttrs = 1;
    cudaLaunchKernelEx(&cfgD, kD, out);
}